// round 4
// baseline (speedup 1.0000x reference)
#include <cuda_runtime.h>
#include <cstdio>
#include <cstdint>

// ---------------------------------------------------------------------------
// Batched greedy nearest-neighbor (B=64, N=1000).
//   distance (B,N,N) f32 | mask (B,N) bool-ish | start_idx (B,) int-ish |
//   pad_value (1,) scalar -> pred (B,N) ++ pred_len (B,)  [written as f32]
//
// One warp per batch. Visited mask in registers (32 cols/lane). Per step:
// 8x LDG.128/lane fetches the current row, packed-u64 (bits<<32|col) argmin
// via shfl butterfly (ties -> lowest col == jnp.argmin). Active step count
// C == popcount of initially-unvisited nodes, so only C <= N steps run.
// Inputs identified by element count; elem widths detected at runtime.
// ---------------------------------------------------------------------------

#define MK_BYTE  0   // u8 bool
#define MK_WORD  1   // i32 / f32 (word != 0 is truth)
#define MK_DWORD 2   // i64 (low word at stride 2)
#define MK_HALF  3   // u16 / bf16 / f16 (halfword != 0 is truth)

#define SK_I32 0
#define SK_I64 1
#define SK_F32 2

__device__ int g_mask_kind, g_start_kind, g_pad;

__global__ void detect_kernel(const unsigned int* __restrict__ mw, int m_nwords,
                              const unsigned int* __restrict__ sw, int s_nwords,
                              const unsigned int* __restrict__ pw, int has_pad,
                              int N)
{
    __shared__ int vi_word, vi_dword, vi_half, s_odd_nz, s_small_int, s_nonfloat;
    if (threadIdx.x == 0) {
        vi_word = 0; vi_dword = 0; vi_half = 0;
        s_odd_nz = 0; s_small_int = 0; s_nonfloat = 0;
    }
    __syncthreads();

    // ---- mask word-pattern scan ------------------------------------------
    int a = 0, b = 0, c = 0;
    for (int i = threadIdx.x; i < m_nwords; i += blockDim.x) {
        unsigned int v = mw[i];
        if (v != 0u && v != 1u && v != 0x3F800000u) a = 1;          // not i32/f32
        if ((i & 1) ? (v != 0u) : (v > 1u)) b = 1;                  // not i64 0/1
        unsigned int h0 = v & 0xFFFFu, h1 = v >> 16;                // not 16-bit
        if (!(h0 == 0u || h0 == 1u || h0 == 0x3F80u || h0 == 0x3C00u)) c = 1;
        if (!(h1 == 0u || h1 == 1u || h1 == 0x3F80u || h1 == 0x3C00u)) c = 1;
    }
    if (a) vi_word = 1;
    if (b) vi_dword = 1;
    if (c) vi_half = 1;

    // ---- start_idx scan ---------------------------------------------------
    int o = 0, si = 0, nf = 0;
    for (int i = threadIdx.x; i < s_nwords; i += blockDim.x) {
        unsigned int v = sw[i];
        if ((i & 1) && v != 0u) o = 1;                 // odd word nonzero
        if (v >= 1u && v < 0x01000000u) si = 1;        // small positive int seen
        if (!(v == 0u || (v >= 0x30000000u && v < 0x45000000u))) nf = 1;
    }
    if (o)  s_odd_nz = 1;
    if (si) s_small_int = 1;
    if (nf) s_nonfloat = 1;
    __syncthreads();

    if (threadIdx.x == 0) {
        int mk;
        if      (!vi_word)  mk = MK_WORD;
        else if (!vi_dword) mk = MK_DWORD;
        else if (!vi_half)  mk = MK_HALF;
        else                mk = MK_BYTE;
        g_mask_kind = mk;

        int sk;
        if      (!s_odd_nz && s_nwords >= 2)  sk = SK_I64;
        else if (!s_nonfloat && !s_small_int) sk = SK_F32;
        else                                  sk = SK_I32;
        g_start_kind = sk;

        // ---- pad scalar: i32 / i64 / f32 / f64, fallback N ---------------
        int pad = N;
        if (has_pad) {
            unsigned int p0 = pw[0];
            if (p0 < 0x01000000u) {                    // plausible small int
                pad = (int)p0;
                if (p0 == 0u) {                        // maybe f64 low word
                    unsigned int p1 = pw[1];
                    if (p1 >= 0x3FF00000u && p1 < 0x42000000u)
                        pad = (int)__hiloint2double((int)p1, 0);
                }
            } else {
                float f = __uint_as_float(p0);
                if (f >= 0.0f && f < 16777216.0f) pad = (int)f;
            }
        }
        g_pad = pad;
    }
}

__global__ __launch_bounds__(32, 1)
void greedy_nn_kernel(const float* __restrict__ dist,
                      const void*  __restrict__ mask,
                      const void*  __restrict__ start_idx,
                      float*       __restrict__ out,      // <- FLOAT output
                      int B, int N, int write_len)
{
    const int b    = blockIdx.x;
    const int lane = threadIdx.x;
    const int mk   = g_mask_kind;
    const int sk   = g_start_kind;
    const float padf = (float)g_pad;
    const int nf4  = (N + 3) >> 2;
    const unsigned int BIGBITS = 0x49742400u;      // bits of 1.0e6f

    // ---- per-lane 32-bit visited mask; lane owns cols 4*(lane+32q)+r ------
    unsigned int m = 0;
    const unsigned char*  m8  = (const unsigned char*)mask;
    const unsigned short* m16 = (const unsigned short*)mask;
    const unsigned int*   m32 = (const unsigned int*)mask;
    #pragma unroll
    for (int q = 0; q < 8; q++) {
        #pragma unroll
        for (int r = 0; r < 4; r++) {
            int col = 4 * (lane + 32 * q) + r;
            bool mb = true;                        // out-of-range -> visited
            if (col < N) {
                int off = b * N + col;
                if      (mk == MK_WORD)  mb = (m32[off]     != 0u);
                else if (mk == MK_BYTE)  mb = (m8[off]      != 0u);
                else if (mk == MK_HALF)  mb = (m16[off]     != 0u);
                else                     mb = (m32[2 * off] != 0u);
            }
            if (mb) m |= 1u << (q * 4 + r);
        }
    }

    // ---- active step count C = # initially-unvisited nodes ----------------
    unsigned int cnt = 32u - (unsigned)__popc(m);
    #pragma unroll
    for (int off = 16; off; off >>= 1)
        cnt += __shfl_xor_sync(0xffffffffu, cnt, off);
    const int C = (int)cnt;

    // ---- start point, dtype-aware ----------------------------------------
    int point;
    {
        const int* s32 = (const int*)start_idx;
        if      (sk == SK_I64) point = s32[2 * b];
        else if (sk == SK_F32) point = (int)((const float*)start_idx)[b];
        else                   point = s32[b];
    }
    if (point < 0) point = 0;
    if (point >= N) point = N - 1;

    const float* dbase = dist + (size_t)b * N * N;
    float* pred = out + (size_t)b * N;

    // ---- sequential greedy chain -----------------------------------------
    for (int t = 0; t < C; t++) {
        const float4* row = (const float4*)(dbase + (size_t)point * N);

        float4 v[8];
        #pragma unroll
        for (int q = 0; q < 8; q++) {
            int f = lane + 32 * q;
            v[q] = (f < nf4) ? row[f] : make_float4(0.f, 0.f, 0.f, 0.f);
        }

        unsigned long long best = ~0ull;
        #pragma unroll
        for (int q = 0; q < 8; q++) {
            int f = lane + 32 * q;
            const float* pv = (const float*)&v[q];
            #pragma unroll
            for (int r = 0; r < 4; r++) {
                unsigned int fb = ((m >> (q * 4 + r)) & 1u)
                                  ? BIGBITS : __float_as_uint(pv[r]);
                unsigned long long key =
                    ((unsigned long long)fb << 32) | (unsigned int)(4 * f + r);
                best = key < best ? key : best;
            }
        }
        #pragma unroll
        for (int off = 16; off; off >>= 1) {
            unsigned long long o = __shfl_xor_sync(0xffffffffu, best, off);
            best = o < best ? o : best;
        }

        int idx = (int)(unsigned int)best;
        if (lane == 0) pred[t] = (float)idx;       // float write

        int f = idx >> 2;
        if ((f & 31) == lane)
            m |= 1u << (((f >> 5) << 2) | (idx & 3));
        point = idx;
    }

    // ---- pad tail + pred_len (float) --------------------------------------
    for (int t = C + lane; t < N; t += 32) pred[t] = padf;
    if (write_len && lane == 0) out[(size_t)B * N + b] = (float)C;
}

extern "C" void kernel_launch(void* const* d_in, const int* in_sizes, int n_in,
                              void* d_out, int out_size)
{
    // ---- identify inputs by element count (order-proof) -------------------
    int di = 0, mi = -1, si = -1, pi = -1;
    for (int i = 1; i < n_in; i++)
        if (in_sizes[i] > in_sizes[di]) di = i;            // distance: largest
    for (int i = 0; i < n_in; i++) {
        if (i == di) continue;
        if (pi < 0 || in_sizes[i] < in_sizes[pi]) pi = i;  // pad: smallest
    }
    for (int i = 0; i < n_in; i++) {
        if (i == di || i == pi) continue;
        if (mi < 0) { mi = i; continue; }
        si = i;
    }
    if (si >= 0 && in_sizes[si] > in_sizes[mi]) { int t = mi; mi = si; si = t; }
    if (si < 0) { si = pi; pi = -1; }                      // only 3 inputs

    const float* dist  = (const float*)d_in[di];
    const void*  mask  = d_in[mi];
    const void*  start = d_in[si];
    const void*  padp  = (pi >= 0) ? d_in[pi] : nullptr;

    const int B = in_sizes[si];
    const int N = in_sizes[mi] / B;

    // Host-side diagnostics (only runs on correctness + capture calls).
    printf("DBG0 n_in=%d sizes=", n_in);
    for (int i = 0; i < n_in; i++) printf("%d,", in_sizes[i]);
    printf(" out_size=%d map(d,m,s,p)=%d,%d,%d,%d B=%d N=%d\n",
           out_size, di, mi, si, pi, B, N);
    fflush(stdout);

    int m_nwords = in_sizes[mi] / 4;       // in-bounds for every candidate width
    int s_nwords = in_sizes[si];
    detect_kernel<<<1, 256>>>((const unsigned int*)mask, m_nwords,
                              (const unsigned int*)start, s_nwords,
                              padp ? (const unsigned int*)padp
                                   : (const unsigned int*)start,
                              padp ? 1 : 0, N);

    int write_len = (out_size >= B * N + B) ? 1 : 0;
    greedy_nn_kernel<<<B, 32>>>(dist, mask, start, (float*)d_out,
                                B, N, write_len);
}

// round 5
// speedup vs baseline: 5.5962x; 5.5962x over previous
#include <cuda_runtime.h>
#include <cstdio>
#include <cstdint>

// ---------------------------------------------------------------------------
// Batched greedy nearest-neighbor (B=64, N=1000), latency-chain optimized.
// One 128-thread CTA per batch. Each thread owns 2 float4 row slots (covers
// N <= 1024). Per step:
//   2x asm ld.global.nc.v4.f32 (order-guaranteed, MLP=2, ~1 DRAM round-trip)
//   8-elem local argmin (32-bit bits/col pair, ascending col => ties->lowest)
//   warp REDUX min(value) + REDUX min(col among value-matchers)
//   4-warp combine via 2x-buffered smem u64 keys, ONE __syncthreads/step
// Active-step count C = popcount(~mask0); tail is pad fill.
// Output written as float32 (harness __output__ dtype).
// ---------------------------------------------------------------------------

#define MK_BYTE  0   // u8 bool
#define MK_WORD  1   // i32 / f32 (word != 0 is truth)
#define MK_DWORD 2   // i64 (low word at stride 2)
#define MK_HALF  3   // u16 / bf16 / f16

#define SK_I32 0
#define SK_I64 1
#define SK_F32 2

__device__ int g_mask_kind, g_start_kind, g_pad;

__global__ void detect_kernel(const unsigned int* __restrict__ mw, int m_nwords,
                              const unsigned int* __restrict__ sw, int s_nwords,
                              const unsigned int* __restrict__ pw, int has_pad,
                              int N)
{
    __shared__ int vi_word, vi_dword, vi_half, s_odd_nz, s_small_int, s_nonfloat;
    if (threadIdx.x == 0) {
        vi_word = 0; vi_dword = 0; vi_half = 0;
        s_odd_nz = 0; s_small_int = 0; s_nonfloat = 0;
    }
    __syncthreads();

    int a = 0, b = 0, c = 0;
    for (int i = threadIdx.x; i < m_nwords; i += blockDim.x) {
        unsigned int v = mw[i];
        if (v != 0u && v != 1u && v != 0x3F800000u) a = 1;
        if ((i & 1) ? (v != 0u) : (v > 1u)) b = 1;
        unsigned int h0 = v & 0xFFFFu, h1 = v >> 16;
        if (!(h0 == 0u || h0 == 1u || h0 == 0x3F80u || h0 == 0x3C00u)) c = 1;
        if (!(h1 == 0u || h1 == 1u || h1 == 0x3F80u || h1 == 0x3C00u)) c = 1;
    }
    if (a) vi_word = 1;
    if (b) vi_dword = 1;
    if (c) vi_half = 1;

    int o = 0, si = 0, nf = 0;
    for (int i = threadIdx.x; i < s_nwords; i += blockDim.x) {
        unsigned int v = sw[i];
        if ((i & 1) && v != 0u) o = 1;
        if (v >= 1u && v < 0x01000000u) si = 1;
        if (!(v == 0u || (v >= 0x30000000u && v < 0x45000000u))) nf = 1;
    }
    if (o)  s_odd_nz = 1;
    if (si) s_small_int = 1;
    if (nf) s_nonfloat = 1;
    __syncthreads();

    if (threadIdx.x == 0) {
        int mk;
        if      (!vi_word)  mk = MK_WORD;
        else if (!vi_dword) mk = MK_DWORD;
        else if (!vi_half)  mk = MK_HALF;
        else                mk = MK_BYTE;
        g_mask_kind = mk;

        int sk;
        if      (!s_odd_nz && s_nwords >= 2)  sk = SK_I64;
        else if (!s_nonfloat && !s_small_int) sk = SK_F32;
        else                                  sk = SK_I32;
        g_start_kind = sk;

        int pad = N;
        if (has_pad) {
            unsigned int p0 = pw[0];
            if (p0 < 0x01000000u) {
                pad = (int)p0;
                if (p0 == 0u) {
                    unsigned int p1 = pw[1];
                    if (p1 >= 0x3FF00000u && p1 < 0x42000000u)
                        pad = (int)__hiloint2double((int)p1, 0);
                }
            } else {
                float f = __uint_as_float(p0);
                if (f >= 0.0f && f < 16777216.0f) pad = (int)f;
            }
        }
        g_pad = pad;
    }
}

__device__ __forceinline__ float4 ldg128_nc(const float* p) {
    float4 v;
    asm volatile("ld.global.nc.v4.f32 {%0,%1,%2,%3}, [%4];"
                 : "=f"(v.x), "=f"(v.y), "=f"(v.z), "=f"(v.w)
                 : "l"(p));
    return v;
}

__global__ __launch_bounds__(128, 1)
void greedy_nn_kernel(const float* __restrict__ dist,
                      const void*  __restrict__ mask,
                      const void*  __restrict__ start_idx,
                      float*       __restrict__ out,
                      int B, int N, int write_len)
{
    __shared__ unsigned long long sbuf[2][4];
    __shared__ int scnt[4];

    const int b    = blockIdx.x;
    const int tid  = threadIdx.x;
    const int lane = tid & 31;
    const int wid  = tid >> 5;
    const int mk   = g_mask_kind;
    const int sk   = g_start_kind;
    const float padf = (float)g_pad;
    const int nf4  = N >> 2;                       // full float4s per row
    const unsigned int BIGBITS = 0x49742400u;      // bits of 1.0e6f

    // slot validity (constant per thread): slot0 f=tid, slot1 f=tid+128
    const bool v0 = (tid       < nf4);
    const bool v1 = (tid + 128 < nf4);

    // ---- visited bits: slot s, r -> col 4*(tid+128s)+r, bit s*4+r ---------
    unsigned int m = 0;
    {
        const unsigned char*  m8  = (const unsigned char*)mask;
        const unsigned short* m16 = (const unsigned short*)mask;
        const unsigned int*   m32 = (const unsigned int*)mask;
        #pragma unroll
        for (int s = 0; s < 2; s++) {
            #pragma unroll
            for (int r = 0; r < 4; r++) {
                int col = 4 * (tid + 128 * s) + r;
                bool mb = true;                    // out-of-range -> visited
                if (col < N) {
                    int off = b * N + col;
                    if      (mk == MK_WORD)  mb = (m32[off]     != 0u);
                    else if (mk == MK_BYTE)  mb = (m8[off]      != 0u);
                    else if (mk == MK_HALF)  mb = (m16[off]     != 0u);
                    else                     mb = (m32[2 * off] != 0u);
                }
                if (mb) m |= 1u << (s * 4 + r);
            }
        }
    }

    // ---- active step count C = # initially-unvisited nodes ----------------
    {
        unsigned int cnt = 8u - (unsigned)__popc(m);
        cnt = __reduce_add_sync(0xffffffffu, cnt);
        if (lane == 0) scnt[wid] = (int)cnt;
    }
    __syncthreads();
    const int C = scnt[0] + scnt[1] + scnt[2] + scnt[3];

    // ---- start point, dtype-aware ----------------------------------------
    int point;
    {
        const int* s32 = (const int*)start_idx;
        if      (sk == SK_I64) point = s32[2 * b];
        else if (sk == SK_F32) point = (int)((const float*)start_idx)[b];
        else                   point = s32[b];
    }
    if (point < 0) point = 0;
    if (point >= N) point = N - 1;

    const float* dbase = dist + (size_t)b * N * N;
    float* pred = out + (size_t)b * N;

    // ---- sequential greedy chain -----------------------------------------
    for (int t = 0; t < C; t++) {
        const float* rp = dbase + (size_t)point * N;

        // both loads issued back-to-back (asm volatile: order guaranteed)
        float4 a = v0 ? ldg128_nc(rp + 4 * tid)
                      : make_float4(1e6f, 1e6f, 1e6f, 1e6f);
        float4 c = v1 ? ldg128_nc(rp + 4 * (tid + 128))
                      : make_float4(1e6f, 1e6f, 1e6f, 1e6f);

        // local argmin over 8 elems (ascending col => strict '<' keeps lowest)
        unsigned int bb = BIGBITS, bc = 0;
        const float* pa = (const float*)&a;
        const float* pc = (const float*)&c;
        #pragma unroll
        for (int r = 0; r < 4; r++) {
            unsigned int fb = ((m >> r) & 1u) ? BIGBITS : __float_as_uint(pa[r]);
            if (fb < bb) { bb = fb; bc = 4 * tid + r; }
        }
        #pragma unroll
        for (int r = 0; r < 4; r++) {
            unsigned int fb = ((m >> (4 + r)) & 1u) ? BIGBITS : __float_as_uint(pc[r]);
            if (fb < bb) { bb = fb; bc = 4 * (tid + 128) + r; }
        }

        // warp reduce: hardware REDUX min on value, then on col among matchers
        unsigned int wmin = __reduce_min_sync(0xffffffffu, bb);
        unsigned int colc = (bb == wmin) ? bc : 0xFFFFFFFFu;
        unsigned int wcol = __reduce_min_sync(0xffffffffu, colc);

        // cross-warp combine via double-buffered smem (one barrier per step)
        if (lane == 0)
            sbuf[t & 1][wid] = ((unsigned long long)wmin << 32) | wcol;
        __syncthreads();
        unsigned long long k0 = sbuf[t & 1][0], k1 = sbuf[t & 1][1];
        unsigned long long k2 = sbuf[t & 1][2], k3 = sbuf[t & 1][3];
        unsigned long long ka = k0 < k1 ? k0 : k1;
        unsigned long long kb = k2 < k3 ? k2 : k3;
        unsigned long long k  = ka < kb ? ka : kb;

        int idx = (int)(unsigned int)k;
        if (tid == 0) pred[t] = (float)idx;

        // owner thread marks idx visited: f = idx>>2, owner tid = f & 127
        int f = idx >> 2;
        if ((f & 127) == tid)
            m |= 1u << (((f >> 7) << 2) | (idx & 3));
        point = idx;
    }

    // ---- pad tail + pred_len (float) --------------------------------------
    for (int t = C + tid; t < N; t += 128) pred[t] = padf;
    if (write_len && tid == 0) out[(size_t)B * N + b] = (float)C;
}

extern "C" void kernel_launch(void* const* d_in, const int* in_sizes, int n_in,
                              void* d_out, int out_size)
{
    // ---- identify inputs by element count (order-proof) -------------------
    int di = 0, mi = -1, si = -1, pi = -1;
    for (int i = 1; i < n_in; i++)
        if (in_sizes[i] > in_sizes[di]) di = i;            // distance: largest
    for (int i = 0; i < n_in; i++) {
        if (i == di) continue;
        if (pi < 0 || in_sizes[i] < in_sizes[pi]) pi = i;  // pad: smallest
    }
    for (int i = 0; i < n_in; i++) {
        if (i == di || i == pi) continue;
        if (mi < 0) { mi = i; continue; }
        si = i;
    }
    if (si >= 0 && in_sizes[si] > in_sizes[mi]) { int t = mi; mi = si; si = t; }
    if (si < 0) { si = pi; pi = -1; }                      // only 3 inputs

    const float* dist  = (const float*)d_in[di];
    const void*  mask  = d_in[mi];
    const void*  start = d_in[si];
    const void*  padp  = (pi >= 0) ? d_in[pi] : nullptr;

    const int B = in_sizes[si];
    const int N = in_sizes[mi] / B;

    int m_nwords = in_sizes[mi] / 4;
    int s_nwords = in_sizes[si];
    detect_kernel<<<1, 256>>>((const unsigned int*)mask, m_nwords,
                              (const unsigned int*)start, s_nwords,
                              padp ? (const unsigned int*)padp
                                   : (const unsigned int*)start,
                              padp ? 1 : 0, N);

    int write_len = (out_size >= B * N + B) ? 1 : 0;
    greedy_nn_kernel<<<B, 128>>>(dist, mask, start, (float*)d_out,
                                 B, N, write_len);
}